// round 16
// baseline (speedup 1.0000x reference)
#include <cuda_runtime.h>

typedef unsigned long long ull;

#define NLAYER 4
#define TSEQ   34
#define VOCAB  14
#define BSEQ   16
#define TROWS  17
#define NTHR   (BSEQ * TROWS)     // 272
#define KV_STRIDE 412             // floats per seq (34*12=408 used, padded for banks)
#define BUF    (BSEQ * KV_STRIDE) // 6592 floats per kv buffer
#define DYN_FLOATS (2 * BUF)
#define DYN_BYTES  (DYN_FLOATS * 4)   // 52736 B
#define OFF_IDX BUF               // idx ints live in buf1 during prologue only
#define LW 112
#define OFF_LNF_W 448
#define OFF_LNF_B 454
#define OFF_HEAD  460             // 84 floats (7 vocab-pairs x 6)
#define OFF_TOK   544             // 42
#define OFF_POS   586             // 102
#define W_TOTAL   688

__device__ __forceinline__ ull pk(float lo, float hi) {
    ull r; asm("mov.b64 %0,{%1,%2};" : "=l"(r) : "f"(lo), "f"(hi)); return r;
}
__device__ __forceinline__ void upk(ull v, float& lo, float& hi) {
    asm("mov.b64 {%0,%1},%2;" : "=f"(lo), "=f"(hi) : "l"(v));
}
__device__ __forceinline__ ull ffma2(ull a, ull b, ull c) {
    ull d; asm("fma.rn.f32x2 %0,%1,%2,%3;" : "=l"(d) : "l"(a), "l"(b), "l"(c)); return d;
}
__device__ __forceinline__ ull fmul2(ull a, ull b) {
    ull d; asm("mul.rn.f32x2 %0,%1,%2;" : "=l"(d) : "l"(a), "l"(b)); return d;
}
__device__ __forceinline__ ull fadd2(ull a, ull b) {
    ull d; asm("add.rn.f32x2 %0,%1,%2;" : "=l"(d) : "l"(a), "l"(b)); return d;
}
__device__ __forceinline__ float ex2f(float x) {
    float r; asm("ex2.approx.f32 %0,%1;" : "=f"(r) : "f"(x)); return r;
}
__device__ __forceinline__ float rcpf(float x) {
    float r; asm("rcp.approx.f32 %0,%1;" : "=f"(r) : "f"(x)); return r;
}
__device__ __forceinline__ ull exp2pair(ull s) {
    float a, b; upk(s, a, b); return pk(ex2f(a), ex2f(b));
}
__device__ __forceinline__ ull dot2(const ull* q, const ull* k) {
    return ffma2(q[0], k[0], ffma2(q[1], k[1], fmul2(q[2], k[2])));
}

__device__ __forceinline__ void lnorm(const float* x, const float* w, const float* b, float* h) {
    float m = (x[0] + x[1] + x[2] + x[3] + x[4] + x[5]) * (1.f / 6.f);
    float var = 0.f;
    #pragma unroll
    for (int d = 0; d < 6; d++) { float c = x[d] - m; var += c * c; h[d] = c; }
    float inv = rsqrtf(var * (1.f / 6.f) + 1e-5f);
    #pragma unroll
    for (int d = 0; d < 6; d++) h[d] = h[d] * inv * w[d] + b[d];
}

__global__ void __launch_bounds__(NTHR, 3)
addtx_kernel(const int* __restrict__ idx,
             const float* __restrict__ tok_emb, const float* __restrict__ pos_enc,
             const float* __restrict__ ln_w,   const float* __restrict__ ln_b,
             const float* __restrict__ q1w,    const float* __restrict__ k1w,
             const float* __restrict__ v1w,    const float* __restrict__ q2w,
             const float* __restrict__ k2w,    const float* __restrict__ v2w,
             const float* __restrict__ out_w,  const float* __restrict__ lnf_w,
             const float* __restrict__ lnf_b,  const float* __restrict__ head_w,
             float* __restrict__ out)
{
    __shared__ __align__(16) float W[W_TOTAL];
    extern __shared__ __align__(16) float U[];  // kv buf0 | kv buf1 (idx during prologue)

    const int s   = threadIdx.x;        // seq in block 0..15
    const int ty  = threadIdx.y;        // row 0..16; warp w = rows {2w, 2w+1}; row 16 = half warp
    const int tid = ty * BSEQ + s;
    const int b   = blockIdx.x * BSEQ + s;
    // SMSP-balanced pair assignment (warp w -> SMSP w%4):
    //   warps 0..3 (ty 0..7):  pr = ty + 1            -> trips {4, 8, 12, 16}
    //   warps 4..7 (ty 8..15): pr = 23 - 2w + (ty&1)  -> trips {32, 28, 24, 20}
    //   half warp (ty 16):     pr = 0                 -> trips 0
    // SMSP loop load per block: (4+32)=(8+28)=(12+24)=(16+20)=36 on every SMSP.
    const int pr  = (ty == 16) ? 0
                  : (ty < 8)   ? (ty + 1)
                               : (23 - (ty & ~1) + (ty & 1));
    const int ta  = 2 * pr, tb = ta + 1;

    // ---- coalesced idx staging (544 ints = 272 int2, one per thread) ----
    ((int2*)(U + OFF_IDX))[tid] = ((const int2*)(idx + (size_t)blockIdx.x * BSEQ * TSEQ))[tid];

    // ---- stage weights as (head1, head2) pairs ----
    const float SCL = 0.83298066476f;   // (1/sqrt(3)) * log2(e), folded into q weights
    for (int i = tid; i < NLAYER * 9; i += NTHR) {
        int l = i / 9, r = i - l * 9;
        float* Wl = W + l * LW;
        Wl[     2 * r    ] = q1w[i] * SCL;
        Wl[     2 * r + 1] = q2w[i] * SCL;
        Wl[18 + 2 * r    ] = k1w[i];
        Wl[18 + 2 * r + 1] = k2w[i];
        Wl[36 + 2 * r    ] = v1w[i];
        Wl[36 + 2 * r + 1] = v2w[i];
    }
    for (int i = tid; i < NLAYER * 18; i += NTHR) {
        int l = i / 18, p2 = i - l * 18, dp = p2 / 6, col = p2 - dp * 6;
        W[l * LW + 54 + 2 * p2    ] = out_w[l * 36 + (2 * dp    ) * 6 + col];
        W[l * LW + 54 + 2 * p2 + 1] = out_w[l * 36 + (2 * dp + 1) * 6 + col];
    }
    for (int i = tid; i < NLAYER * 6; i += NTHR) {
        int l = i / 6, r = i - l * 6;
        W[l * LW + 90 + r] = ln_w[i];
        W[l * LW + 96 + r] = ln_b[i];
    }
    if (tid < 6) { W[OFF_LNF_W + tid] = lnf_w[tid]; W[OFF_LNF_B + tid] = lnf_b[tid]; }
    for (int i = tid; i < 42; i += NTHR) {          // 7 vocab-pairs x 6 dims
        int vp = i / 6, d = i - vp * 6;
        W[OFF_HEAD + 2 * i    ] = head_w[(2 * vp    ) * 6 + d];
        W[OFF_HEAD + 2 * i + 1] = head_w[(2 * vp + 1) * 6 + d];
    }
    for (int i = tid; i < VOCAB * 3; i += NTHR) W[OFF_TOK + i] = tok_emb[i];
    for (int i = tid; i < TSEQ * 3; i += NTHR)  W[OFF_POS + i] = pos_enc[i];
    __syncthreads();

    // ---- embeddings for both owned tokens (idx from smem) ----
    const int tok_a = ((const int*)(U + OFF_IDX))[s * TSEQ + ta];
    const int tok_b = ((const int*)(U + OFF_IDX))[s * TSEQ + tb];
    float xa[6], xb[6];
    #pragma unroll
    for (int d = 0; d < 3; d++) {
        xa[d]     = W[OFF_TOK + tok_a * 3 + d];
        xa[d + 3] = W[OFF_POS + ta * 3 + d];
        xb[d]     = W[OFF_TOK + tok_b * 3 + d];
        xb[d + 3] = W[OFF_POS + tb * 3 + d];
    }

    #pragma unroll
    for (int l = 0; l < NLAYER; l++) {
        const float* Wl = W + l * LW;
        const ull* WQ = (const ull*)(Wl);
        const ull* WK = (const ull*)(Wl + 18);
        const ull* WV = (const ull*)(Wl + 36);
        const ull* WO = (const ull*)(Wl + 54);
        // double-buffered kv: layer l uses buffer (l & 1) -> one barrier per layer
        float* buf = U + (l & 1) * BUF;
        ulonglong2* kvw = (ulonglong2*)(buf + s * KV_STRIDE);
        const ulonglong2* kvr = kvw;

        float ha[6], hb[6];
        lnorm(xa, Wl + 90, Wl + 96, ha);
        lnorm(xb, Wl + 90, Wl + 96, hb);

        ull hpa[3] = { pk(ha[0], ha[3]), pk(ha[1], ha[4]), pk(ha[2], ha[5]) };
        ull hpb[3] = { pk(hb[0], hb[3]), pk(hb[1], hb[4]), pk(hb[2], hb[5]) };

        ull qa[3], ka[3], va[3], qb[3], kb[3], vb[3];
        #pragma unroll
        for (int d = 0; d < 3; d++) {
            ull aq = 0, ak = 0, av = 0, bq = 0, bk = 0, bv = 0;
            #pragma unroll
            for (int e = 0; e < 3; e++) {
                ull wq = WQ[d * 3 + e], wk = WK[d * 3 + e], wv = WV[d * 3 + e];
                aq = ffma2(wq, hpa[e], aq);  bq = ffma2(wq, hpb[e], bq);
                ak = ffma2(wk, hpa[e], ak);  bk = ffma2(wk, hpb[e], bk);
                av = ffma2(wv, hpa[e], av);  bv = ffma2(wv, hpb[e], bv);
            }
            qa[d] = aq; ka[d] = ak; va[d] = av;
            qb[d] = bq; kb[d] = bk; vb[d] = bv;
        }

        // publish k/v (pair-interleaved): {k0,k1},{k2,v0},{v1,v2}
        kvw[ta * 3 + 0] = make_ulonglong2(ka[0], ka[1]);
        kvw[ta * 3 + 1] = make_ulonglong2(ka[2], va[0]);
        kvw[ta * 3 + 2] = make_ulonglong2(va[1], va[2]);
        kvw[tb * 3 + 0] = make_ulonglong2(kb[0], kb[1]);
        kvw[tb * 3 + 1] = make_ulonglong2(kb[2], vb[0]);
        kvw[tb * 3 + 2] = make_ulonglong2(vb[1], vb[2]);
        __syncthreads();   // single barrier per layer (publish -> read)

        // self / cross terms straight from registers (j = ta for a; j = ta, tb for b)
        ull eaa = exp2pair(dot2(qa, ka));
        ull suma = eaa;
        ull aac0 = fmul2(eaa, va[0]), aac1 = fmul2(eaa, va[1]), aac2 = fmul2(eaa, va[2]);

        ull eba = exp2pair(dot2(qb, ka));
        ull ebb = exp2pair(dot2(qb, kb));
        ull sumb = fadd2(eba, ebb);
        ull bac0 = ffma2(eba, va[0], fmul2(ebb, vb[0]));
        ull bac1 = ffma2(eba, va[1], fmul2(ebb, vb[1]));
        ull bac2 = ffma2(eba, va[2], fmul2(ebb, vb[2]));

        // shared causal loop: one kv load serves both query tokens,
        // running pointer + 1-iteration prefetch
        const ulonglong2* kp = kvr;
        ulonglong2 n0 = kp[0], n1 = kp[1], n2 = kp[2];
        #pragma unroll 2
        for (int j = 0; j < ta; j++) {
            ulonglong2 p0 = n0, p1 = n1, p2 = n2;
            kp += 3;
            n0 = kp[0];
            n1 = kp[1];
            n2 = kp[2];
            ull sa = ffma2(qa[0], p0.x, ffma2(qa[1], p0.y, fmul2(qa[2], p1.x)));
            ull sb = ffma2(qb[0], p0.x, ffma2(qb[1], p0.y, fmul2(qb[2], p1.x)));
            ull ea = exp2pair(sa);
            ull eb = exp2pair(sb);
            suma = fadd2(suma, ea);       sumb = fadd2(sumb, eb);
            aac0 = ffma2(ea, p1.y, aac0); bac0 = ffma2(eb, p1.y, bac0);
            aac1 = ffma2(ea, p2.x, aac1); bac1 = ffma2(eb, p2.x, bac1);
            aac2 = ffma2(ea, p2.y, aac2); bac2 = ffma2(eb, p2.y, bac2);
        }

        // normalize + output projection + residual
        float sa1, sa2, sb1, sb2;
        upk(suma, sa1, sa2); upk(sumb, sb1, sb2);
        ull ra = pk(rcpf(sa1), rcpf(sa2));
        ull rb = pk(rcpf(sb1), rcpf(sb2));
        float cA[6], cB[6];
        { ull t0 = fmul2(aac0, ra), t1 = fmul2(aac1, ra), t2 = fmul2(aac2, ra);
          upk(t0, cA[0], cA[3]); upk(t1, cA[1], cA[4]); upk(t2, cA[2], cA[5]); }
        { ull t0 = fmul2(bac0, rb), t1 = fmul2(bac1, rb), t2 = fmul2(bac2, rb);
          upk(t0, cB[0], cB[3]); upk(t1, cB[1], cB[4]); upk(t2, cB[2], cB[5]); }
        ull cdA[6], cdB[6];
        #pragma unroll
        for (int i = 0; i < 6; i++) { cdA[i] = pk(cA[i], cA[i]); cdB[i] = pk(cB[i], cB[i]); }
        #pragma unroll
        for (int dp = 0; dp < 3; dp++) {
            ull accA = pk(xa[2 * dp], xa[2 * dp + 1]);
            ull accB = pk(xb[2 * dp], xb[2 * dp + 1]);
            #pragma unroll
            for (int i = 0; i < 6; i++) {
                ull wo = WO[dp * 6 + i];
                accA = ffma2(wo, cdA[i], accA);
                accB = ffma2(wo, cdB[i], accB);
            }
            upk(accA, xa[2 * dp], xa[2 * dp + 1]);
            upk(accB, xb[2 * dp], xb[2 * dp + 1]);
        }
    }

    // ---- final LN + lm head (vocab-pair FFMA2), direct 8B stores ----
    float hfa[6], hfb[6];
    lnorm(xa, W + OFF_LNF_W, W + OFF_LNF_B, hfa);
    lnorm(xb, W + OFF_LNF_W, W + OFF_LNF_B, hfb);
    ull hda[6], hdb[6];
    #pragma unroll
    for (int d = 0; d < 6; d++) { hda[d] = pk(hfa[d], hfa[d]); hdb[d] = pk(hfb[d], hfb[d]); }

    const ull* WH = (const ull*)(W + OFF_HEAD);
    ull* oa = (ull*)(out + (size_t)(b * TSEQ + ta) * VOCAB);
    ull* ob = (ull*)(out + (size_t)(b * TSEQ + tb) * VOCAB);
    #pragma unroll
    for (int vp = 0; vp < 7; vp++) {
        ull rA = 0, rB = 0;
        #pragma unroll
        for (int d = 0; d < 6; d++) {
            ull wh = WH[vp * 6 + d];
            rA = ffma2(wh, hda[d], rA);
            rB = ffma2(wh, hdb[d], rB);
        }
        oa[vp] = rA;
        ob[vp] = rB;
    }
}

extern "C" void kernel_launch(void* const* d_in, const int* in_sizes, int n_in,
                              void* d_out, int out_size)
{
    const int*   idx     = (const int*)d_in[0];
    const float* tok_emb = (const float*)d_in[1];
    const float* pos_enc = (const float*)d_in[2];
    const float* ln_w    = (const float*)d_in[3];
    const float* ln_b    = (const float*)d_in[4];
    const float* q1w     = (const float*)d_in[5];
    const float* k1w     = (const float*)d_in[6];
    const float* v1w     = (const float*)d_in[7];
    const float* q2w     = (const float*)d_in[8];
    const float* k2w     = (const float*)d_in[9];
    const float* v2w     = (const float*)d_in[10];
    const float* out_w   = (const float*)d_in[11];
    const float* lnf_w   = (const float*)d_in[12];
    const float* lnf_b   = (const float*)d_in[13];
    const float* head_w  = (const float*)d_in[14];
    float* out = (float*)d_out;

    cudaFuncSetAttribute(addtx_kernel,
                         cudaFuncAttributeMaxDynamicSharedMemorySize, DYN_BYTES);

    const int batch = in_sizes[0] / TSEQ;      // 16384
    dim3 block(BSEQ, TROWS);
    dim3 grid(batch / BSEQ);                   // 1024
    addtx_kernel<<<grid, block, DYN_BYTES>>>(idx, tok_emb, pos_enc, ln_w, ln_b,
                                             q1w, k1w, v1w, q2w, k2w, v2w,
                                             out_w, lnf_w, lnf_b, head_w, out);
}